// round 1
// baseline (speedup 1.0000x reference)
#include <cuda_runtime.h>

// ---------------- problem constants ----------------
#define NA 3
#define GH 52
#define GW 52
#define NCLS 80
#define PLANE (GH*GW)          // 2704
#define EPSF 1e-7f
#define MAXB 32
#define MAXCELL (MAXB*NA*GH*GW)   // 259584

// scaled anchors = ANCHORS / (416/52) = ANCHORS / 8
__constant__ float c_aw[3] = {1.25f, 2.0f, 4.125f};
__constant__ float c_ah[3] = {1.625f, 3.75f, 2.875f};

// ---------------- scratch (no allocs allowed) ----------------
__device__ int           d_winner[MAXCELL];       // last (max) target index per cell, -1 = none
__device__ unsigned char d_ignore[MAXCELL];       // 1 => noobj = 0
__device__ unsigned int  d_clsbits[MAXCELL * 3];  // 80-bit class union per cell
__device__ double        d_acc[4];                // iou_sum, conf1_sum, conf2_sum, cls_sum
__device__ int           d_npos;

// ---------------- kernel 0: zero scratch ----------------
__global__ void k_zero(int ncell) {
    int i = blockIdx.x * blockDim.x + threadIdx.x;
    int stride = gridDim.x * blockDim.x;
    for (int k = i; k < ncell; k += stride) {
        d_winner[k] = -1;
        d_ignore[k] = 0;
        d_clsbits[3*k + 0] = 0u;
        d_clsbits[3*k + 1] = 0u;
        d_clsbits[3*k + 2] = 0u;
    }
    if (i < 4) d_acc[i] = 0.0;
    if (i == 0) d_npos = 0;
}

// ---------------- kernel 1: decode targets ----------------
__global__ void k_decode(const float* __restrict__ targets, int B, int T) {
    int idx = blockIdx.x * blockDim.x + threadIdx.x;
    if (idx >= B * T) return;
    int b = idx / T;
    int t = idx % T;
    const float* tp = targets + (size_t)idx * 5;
    float c = tp[0], x = tp[1], y = tp[2], w = tp[3], h = tp[4];
    if (c + x + y + w + h == 0.0f) return;   // valid = sum != 0 (all comps >= 0)

    float gx = x * GW, gy = y * GH, gw = w * GW, gh = h * GH;
    int gi = (int)gx;
    int gj = (int)gy;
    if (gi < 0 || gi >= GW || gj < 0 || gj >= GH) return;  // JAX OOB scatter: dropped
    int cls = (int)c;

    float area = gw * gh;
    float ious[3];
    float best_iou = -1.0f;
    int best = 0;
#pragma unroll
    for (int a = 0; a < 3; a++) {
        float inter = fminf(gw, c_aw[a]) * fminf(gh, c_ah[a]);
        float iou = inter / (area + c_aw[a] * c_ah[a] - inter + 1e-16f);
        ious[a] = iou;
        if (iou > best_iou) { best_iou = iou; best = a; }   // strict > keeps first (argmax)
    }

    int b3 = b * NA;
#pragma unroll
    for (int a = 0; a < 3; a++)
        if (ious[a] > 0.5f)
            d_ignore[((b3 + a) * GH + gj) * GW + gi] = 1;   // races benign (all write 1)

    int cell = ((b3 + best) * GH + gj) * GW + gi;
    atomicMax(&d_winner[cell], t);                          // emulate last-update-wins
    if (cls >= 0 && cls < NCLS)
        atomicOr(&d_clsbits[cell * 3 + (cls >> 5)], 1u << (cls & 31));
}

// ---------------- kernel 2: main per-cell pass ----------------
__device__ __forceinline__ float warp_sum(float v) {
#pragma unroll
    for (int o = 16; o > 0; o >>= 1) v += __shfl_down_sync(0xffffffffu, v, o);
    return v;
}

__global__ void k_main(const float* __restrict__ input,
                       const float* __restrict__ targets,
                       int B, int T) {
    int idx = blockIdx.x * blockDim.x + threadIdx.x;
    int total = B * NA * GH * GW;

    float s_iou = 0.f, s_c1 = 0.f, s_c2 = 0.f, s_cls = 0.f, s_np = 0.f;

    if (idx < total) {
        int i = idx % GW;
        int tmp = idx / GW;
        int j = tmp % GH;
        tmp /= GH;
        int a = tmp % NA;
        int b = tmp / NA;

        size_t base = (((size_t)b * 255 + (size_t)a * 85) * GH + j) * GW + i;

        float confl = input[base + (size_t)4 * PLANE];
        float conf = 1.0f / (1.0f + expf(-confl));
        float conf_c = fminf(fmaxf(conf, EPSF), 1.0f - EPSF);

        int cell = idx;                        // idx already enumerates (b,a,j,i)
        int wt = d_winner[cell];
        bool m = (wt >= 0);
        bool ign = (d_ignore[cell] != 0);

        const float LOG1MEPS = -logf(1.0f - EPSF);   // bce at p=clip(0)=EPS, t=0
        // term1: bce(conf*mask, mask)
        s_c1 = m ? (-logf(conf_c)) : LOG1MEPS;
        // term2: bce(conf*noobj, 0)
        s_c2 = (!ign) ? (-logf(1.0f - conf_c)) : LOG1MEPS;

        if (m) {
            s_np = 1.0f;
            const float* tp = targets + ((size_t)b * T + wt) * 5;
            float kx = tp[1] * GW, ky = tp[2] * GH;
            float kw = tp[3] * GW, kh = tp[4] * GH;

            float xl = input[base];
            float yl = input[base + (size_t)1 * PLANE];
            float wl = input[base + (size_t)2 * PLANE];
            float hl = input[base + (size_t)3 * PLANE];

            float hx = 1.0f / (1.0f + expf(-xl)) + (float)i;
            float hy = 1.0f / (1.0f + expf(-yl)) + (float)j;
            float hw = expf(wl) * c_aw[a];
            float hh = expf(hl) * c_ah[a];

            float iw = fminf(hx + hw * 0.5f, kx + kw * 0.5f) -
                       fmaxf(hx - hw * 0.5f, kx - kw * 0.5f);
            iw = fmaxf(iw, 0.0f);
            float ih = fminf(hy + hh * 0.5f, ky + kh * 0.5f) -
                       fmaxf(hy - hh * 0.5f, ky - kh * 0.5f);
            ih = fmaxf(ih, 0.0f);
            float inter = iw * ih;
            float iou = inter / (hw * hh + kw * kh - inter + 1e-16f);
            s_iou = 1.0f - iou;

            unsigned bits0 = d_clsbits[cell * 3 + 0];
            unsigned bits1 = d_clsbits[cell * 3 + 1];
            unsigned bits2 = d_clsbits[cell * 3 + 2];
#pragma unroll
            for (int c = 0; c < NCLS; c++) {
                float pl = input[base + (size_t)(5 + c) * PLANE];
                float pc = 1.0f / (1.0f + expf(-pl));
                float p = fminf(fmaxf(pc, EPSF), 1.0f - EPSF);
                unsigned word = (c < 32) ? bits0 : (c < 64 ? bits1 : bits2);
                float tt = ((word >> (c & 31)) & 1u) ? 1.0f : 0.0f;
                s_cls += -(tt * logf(p) + (1.0f - tt) * logf(1.0f - p));
            }
        }
    }

    // block reduction: 256 threads = 8 warps
    s_iou = warp_sum(s_iou);
    s_c1  = warp_sum(s_c1);
    s_c2  = warp_sum(s_c2);
    s_cls = warp_sum(s_cls);
    s_np  = warp_sum(s_np);

    __shared__ float sm[5][8];
    int wid = threadIdx.x >> 5;
    int lid = threadIdx.x & 31;
    if (lid == 0) {
        sm[0][wid] = s_iou; sm[1][wid] = s_c1; sm[2][wid] = s_c2;
        sm[3][wid] = s_cls; sm[4][wid] = s_np;
    }
    __syncthreads();
    if (wid == 0) {
        float v0 = (lid < 8) ? sm[0][lid] : 0.f;
        float v1 = (lid < 8) ? sm[1][lid] : 0.f;
        float v2 = (lid < 8) ? sm[2][lid] : 0.f;
        float v3 = (lid < 8) ? sm[3][lid] : 0.f;
        float v4 = (lid < 8) ? sm[4][lid] : 0.f;
        v0 = warp_sum(v0); v1 = warp_sum(v1); v2 = warp_sum(v2);
        v3 = warp_sum(v3); v4 = warp_sum(v4);
        if (lid == 0) {
            if (v0 != 0.f) atomicAdd(&d_acc[0], (double)v0);
            atomicAdd(&d_acc[1], (double)v1);
            atomicAdd(&d_acc[2], (double)v2);
            if (v3 != 0.f) atomicAdd(&d_acc[3], (double)v3);
            if (v4 != 0.f) atomicAdd(&d_npos, (int)(v4 + 0.5f));
        }
    }
}

// ---------------- kernel 3: finalize ----------------
__global__ void k_final(float* __restrict__ out, int B) {
    double iou = d_acc[0], c1 = d_acc[1], c2 = d_acc[2], cls = d_acc[3];
    int np = d_npos;
    double N = (double)B * NA * GH * GW;
    float loss_iou  = (float)iou;
    float loss_conf = (float)(c1 / N + 0.5 * (c2 / N));
    double npf = (np < 1) ? 1.0 : (double)np;
    float loss_cls  = (float)(cls / (npf * (double)NCLS));
    float loss = 0.5f * loss_iou + loss_conf + loss_cls;
    out[0] = loss;
    out[1] = loss_iou;
    out[2] = loss_conf;
    out[3] = loss_cls;
}

// ---------------- launch ----------------
extern "C" void kernel_launch(void* const* d_in, const int* in_sizes, int n_in,
                              void* d_out, int out_size) {
    const float* input   = (const float*)d_in[0];
    const float* targets = (const float*)d_in[1];

    int B = in_sizes[0] / (255 * GH * GW);
    if (B > MAXB) B = MAXB;
    int T = in_sizes[1] / (B * 5);
    int ncell = B * NA * GH * GW;

    k_zero<<<256, 256>>>(ncell);
    int nt = B * T;
    k_decode<<<(nt + 255) / 256, 256>>>(targets, B, T);
    k_main<<<(ncell + 255) / 256, 256>>>(input, targets, B, T);
    k_final<<<1, 1>>>((float*)d_out, B);
}

// round 2
// speedup vs baseline: 1.1529x; 1.1529x over previous
#include <cuda_runtime.h>

// ---------------- problem constants ----------------
#define NA 3
#define GH 52
#define GW 52
#define NCLS 80
#define PLANE (GH*GW)          // 2704
#define EPSF 1e-7f
#define CHUNK 256
#define NCHUNK ((PLANE + CHUNK - 1) / CHUNK)   // 11

// scaled anchors = ANCHORS / (416/52) = ANCHORS / 8
__constant__ float c_aw[3] = {1.25f, 2.0f, 4.125f};
__constant__ float c_ah[3] = {1.625f, 3.75f, 2.875f};

// ---------------- global accumulators (zero-init at module load; reset by last block) ----
__device__ double       d_acc[4];     // iou_sum, conf1_sum, conf2_sum, cls_sum
__device__ int          d_npos;
__device__ unsigned int d_count;

__device__ __forceinline__ float warp_sum(float v) {
#pragma unroll
    for (int o = 16; o > 0; o >>= 1) v += __shfl_down_sync(0xffffffffu, v, o);
    return v;
}

__global__ void k_fused(const float* __restrict__ input,
                        const float* __restrict__ targets,
                        float* __restrict__ out,
                        int B, int T) {
    // block -> (b, a, chunk)
    int bx    = blockIdx.x;
    int b     = bx / (NA * NCHUNK);
    int rem   = bx % (NA * NCHUNK);
    int a     = rem / NCHUNK;
    int chunk = rem % NCHUNK;
    int p0    = chunk * CHUNK;

    // ---- shared per-chunk target tables ----
    __shared__ int           s_win[CHUNK];        // winner target idx (-1 none)
    __shared__ unsigned int  s_cls[CHUNK * 3];    // 80-bit class union
    __shared__ unsigned char s_ign[CHUNK];        // 1 => noobj = 0
    __shared__ float         s_part[5][8];
    __shared__ int           s_last;

    int tid = threadIdx.x;
    s_win[tid] = -1;
    s_ign[tid] = 0;
    s_cls[tid] = 0u;
    s_cls[tid + CHUNK] = 0u;
    s_cls[tid + 2 * CHUNK] = 0u;
    __syncthreads();

    // ---- in-block target decode (threads cover t = tid, tid+256, ...) ----
    for (int t = tid; t < T; t += blockDim.x) {
        const float* tp = targets + ((size_t)b * T + t) * 5;
        float c = tp[0], x = tp[1], y = tp[2], w = tp[3], h = tp[4];
        if (c + x + y + w + h == 0.0f) continue;          // valid = sum != 0

        float gx = x * GW, gy = y * GH, gw = w * GW, gh = h * GH;
        int gi = (int)gx, gj = (int)gy;
        if (gi < 0 || gi >= GW || gj < 0 || gj >= GH) continue;  // OOB scatter dropped

        int p  = gj * GW + gi;
        int lp = p - p0;
        if (lp < 0 || lp >= CHUNK) continue;

        float area = gw * gh;
        float ious[3];
        float best_iou = -1.0f;
        int best = 0;
#pragma unroll
        for (int k = 0; k < 3; k++) {
            float inter = fminf(gw, c_aw[k]) * fminf(gh, c_ah[k]);
            float iou = inter / (area + c_aw[k] * c_ah[k] - inter + 1e-16f);
            ious[k] = iou;
            if (iou > best_iou) { best_iou = iou; best = k; } // strict > = argmax first
        }

        if (ious[a] > 0.5f) s_ign[lp] = 1;                 // races benign (all write 1)
        if (best == a) {
            atomicMax(&s_win[lp], t);                      // last-update-wins
            int cls = (int)c;
            if (cls >= 0 && cls < NCLS)
                atomicOr(&s_cls[lp + ((cls >> 5) * CHUNK)], 1u << (cls & 31));
        }
    }
    __syncthreads();

    // ---- per-cell loss terms ----
    float s_iou = 0.f, s_c1 = 0.f, s_c2 = 0.f, s_cl = 0.f, s_np = 0.f;

    int p = p0 + tid;
    if (p < PLANE) {
        int j = p / GW;
        int i = p - j * GW;
        size_t base = ((size_t)b * 255 + (size_t)a * 85) * PLANE + p;

        float confl = input[base + (size_t)4 * PLANE];
        float conf  = 1.0f / (1.0f + expf(-confl));
        float conf_c = fminf(fmaxf(conf, EPSF), 1.0f - EPSF);

        int  wt  = s_win[tid];
        bool m   = (wt >= 0);
        bool ign = (s_ign[tid] != 0);

        const float LOG1MEPS = -logf(1.0f - EPSF);   // bce at p=EPS, t=0
        s_c1 = m      ? (-logf(conf_c))        : LOG1MEPS;   // bce(conf*mask, mask)
        s_c2 = (!ign) ? (-logf(1.0f - conf_c)) : LOG1MEPS;   // bce(conf*noobj, 0)

        if (m) {
            s_np = 1.0f;
            const float* tp = targets + ((size_t)b * T + wt) * 5;
            float kx = tp[1] * GW, ky = tp[2] * GH;
            float kw = tp[3] * GW, kh = tp[4] * GH;

            float xl = input[base];
            float yl = input[base + (size_t)1 * PLANE];
            float wl = input[base + (size_t)2 * PLANE];
            float hl = input[base + (size_t)3 * PLANE];

            float hx = 1.0f / (1.0f + expf(-xl)) + (float)i;
            float hy = 1.0f / (1.0f + expf(-yl)) + (float)j;
            float hw = expf(wl) * c_aw[a];
            float hh = expf(hl) * c_ah[a];

            float iw = fminf(hx + hw * 0.5f, kx + kw * 0.5f) -
                       fmaxf(hx - hw * 0.5f, kx - kw * 0.5f);
            iw = fmaxf(iw, 0.0f);
            float ih = fminf(hy + hh * 0.5f, ky + kh * 0.5f) -
                       fmaxf(hy - hh * 0.5f, ky - kh * 0.5f);
            ih = fmaxf(ih, 0.0f);
            float inter = iw * ih;
            float iou = inter / (hw * hh + kw * kh - inter + 1e-16f);
            s_iou = 1.0f - iou;

            unsigned b0 = s_cls[tid];
            unsigned b1 = s_cls[tid + CHUNK];
            unsigned b2 = s_cls[tid + 2 * CHUNK];
#pragma unroll
            for (int c = 0; c < NCLS; c++) {
                float pl = input[base + (size_t)(5 + c) * PLANE];
                float pc = 1.0f / (1.0f + expf(-pl));
                float pp = fminf(fmaxf(pc, EPSF), 1.0f - EPSF);
                unsigned word = (c < 32) ? b0 : (c < 64 ? b1 : b2);
                float tt = ((word >> (c & 31)) & 1u) ? 1.0f : 0.0f;
                s_cl += -(tt * logf(pp) + (1.0f - tt) * logf(1.0f - pp));
            }
        }
    }

    // ---- block reduction (256 threads = 8 warps) ----
    s_iou = warp_sum(s_iou);
    s_c1  = warp_sum(s_c1);
    s_c2  = warp_sum(s_c2);
    s_cl  = warp_sum(s_cl);
    s_np  = warp_sum(s_np);

    int wid = tid >> 5, lid = tid & 31;
    if (lid == 0) {
        s_part[0][wid] = s_iou; s_part[1][wid] = s_c1; s_part[2][wid] = s_c2;
        s_part[3][wid] = s_cl;  s_part[4][wid] = s_np;
    }
    __syncthreads();
    if (wid == 0) {
        float v0 = (lid < 8) ? s_part[0][lid] : 0.f;
        float v1 = (lid < 8) ? s_part[1][lid] : 0.f;
        float v2 = (lid < 8) ? s_part[2][lid] : 0.f;
        float v3 = (lid < 8) ? s_part[3][lid] : 0.f;
        float v4 = (lid < 8) ? s_part[4][lid] : 0.f;
        v0 = warp_sum(v0); v1 = warp_sum(v1); v2 = warp_sum(v2);
        v3 = warp_sum(v3); v4 = warp_sum(v4);
        if (lid == 0) {
            if (v0 != 0.f) atomicAdd(&d_acc[0], (double)v0);
            atomicAdd(&d_acc[1], (double)v1);
            atomicAdd(&d_acc[2], (double)v2);
            if (v3 != 0.f) atomicAdd(&d_acc[3], (double)v3);
            if (v4 != 0.f) atomicAdd(&d_npos, (int)(v4 + 0.5f));
        }
    }

    // ---- last-block finalize + state reset (graph-replay safe) ----
    __threadfence();
    if (tid == 0) {
        unsigned prev = atomicAdd(&d_count, 1u);
        s_last = (prev == gridDim.x - 1) ? 1 : 0;
    }
    __syncthreads();
    if (s_last && tid == 0) {
        double iou = d_acc[0], c1 = d_acc[1], c2 = d_acc[2], cls = d_acc[3];
        int np = d_npos;
        double N = (double)B * NA * GH * GW;
        float loss_iou  = (float)iou;
        float loss_conf = (float)(c1 / N + 0.5 * (c2 / N));
        double npf = (np < 1) ? 1.0 : (double)np;
        float loss_cls  = (float)(cls / (npf * (double)NCLS));
        out[0] = 0.5f * loss_iou + loss_conf + loss_cls;
        out[1] = loss_iou;
        out[2] = loss_conf;
        out[3] = loss_cls;
        // reset for next replay
        d_acc[0] = 0.0; d_acc[1] = 0.0; d_acc[2] = 0.0; d_acc[3] = 0.0;
        d_npos = 0;
        d_count = 0u;
    }
}

extern "C" void kernel_launch(void* const* d_in, const int* in_sizes, int n_in,
                              void* d_out, int out_size) {
    const float* input   = (const float*)d_in[0];
    const float* targets = (const float*)d_in[1];

    int B = in_sizes[0] / (255 * GH * GW);
    int T = in_sizes[1] / (B * 5);

    int nblk = B * NA * NCHUNK;
    k_fused<<<nblk, CHUNK>>>(input, targets, (float*)d_out, B, T);
}

// round 3
// speedup vs baseline: 1.2210x; 1.0591x over previous
#include <cuda_runtime.h>

// ---------------- problem constants ----------------
#define NA 3
#define GH 52
#define GW 52
#define NCLS 80
#define PLANE (GH*GW)             // 2704
#define EPSF 1e-7f
#define LOG1MEPS 1.00000011686097e-07f   // -log(1 - 1e-7)
#define CHUNK 1024                // cells per block
#define NCHUNK 3                  // ceil(2704/1024)
#define TPB 256
#define CPT 4                     // cells per thread

// scaled anchors = ANCHORS / (416/52) = ANCHORS / 8
__constant__ float c_aw[3] = {1.25f, 2.0f, 4.125f};
__constant__ float c_ah[3] = {1.625f, 3.75f, 2.875f};

// ---------------- global accumulators (zero at module load; reset by last block) ----
__device__ double       d_acc[4];     // iou_sum, conf1_sum, conf2_sum, cls_sum
__device__ int          d_npos;
__device__ unsigned int d_count;

__device__ __forceinline__ float warp_sum(float v) {
#pragma unroll
    for (int o = 16; o > 0; o >>= 1) v += __shfl_down_sync(0xffffffffu, v, o);
    return v;
}

__device__ __forceinline__ float fsigmoid(float x) {
    return __fdividef(1.0f, 1.0f + __expf(-x));
}

__global__ void k_fused(const float* __restrict__ input,
                        const float* __restrict__ targets,
                        float* __restrict__ out,
                        int B, int T) {
    // block -> (b, a, chunk)
    int bx    = blockIdx.x;
    int b     = bx / (NA * NCHUNK);
    int rem   = bx % (NA * NCHUNK);
    int a     = rem / NCHUNK;
    int chunk = rem % NCHUNK;
    int p0    = chunk * CHUNK;

    __shared__ int           s_win[CHUNK];        // winner target idx, -1 none
    __shared__ unsigned int  s_cls[CHUNK * 3];    // 80-bit class union
    __shared__ unsigned char s_ign[CHUNK];        // 1 => noobj = 0
    __shared__ float         s_part[5][8];
    __shared__ int           s_last;

    int tid = threadIdx.x;
#pragma unroll
    for (int u = 0; u < CPT; u++) {
        int k = tid + u * TPB;
        s_win[k] = -1;
        s_ign[k] = 0;
        s_cls[k] = 0u;
        s_cls[k + CHUNK] = 0u;
        s_cls[k + 2 * CHUNK] = 0u;
    }
    __syncthreads();

    // ---- in-block target decode ----
    for (int t = tid; t < T; t += TPB) {
        const float* tp = targets + ((size_t)b * T + t) * 5;
        float c = tp[0], x = tp[1], y = tp[2], w = tp[3], h = tp[4];
        if (c + x + y + w + h == 0.0f) continue;          // valid = sum != 0

        float gx = x * GW, gy = y * GH, gw = w * GW, gh = h * GH;
        int gi = (int)gx, gj = (int)gy;
        if (gi < 0 || gi >= GW || gj < 0 || gj >= GH) continue;

        int p  = gj * GW + gi;
        int lp = p - p0;
        if (lp < 0 || lp >= CHUNK) continue;

        float area = gw * gh;
        float ious[3];
        float best_iou = -1.0f;
        int best = 0;
#pragma unroll
        for (int k = 0; k < 3; k++) {
            float inter = fminf(gw, c_aw[k]) * fminf(gh, c_ah[k]);
            float iou = inter / (area + c_aw[k] * c_ah[k] - inter + 1e-16f);
            ious[k] = iou;
            if (iou > best_iou) { best_iou = iou; best = k; } // argmax (first max)
        }

        if (ious[a] > 0.5f) s_ign[lp] = 1;                 // benign races
        if (best == a) {
            atomicMax(&s_win[lp], t);                      // last-update-wins
            int cls = (int)c;
            if (cls >= 0 && cls < NCLS)
                atomicOr(&s_cls[lp + ((cls >> 5) * CHUNK)], 1u << (cls & 31));
        }
    }
    __syncthreads();

    // ---- per-cell loss terms, CPT cells per thread ----
    float a_iou = 0.f, a_c1 = 0.f, a_c2 = 0.f, a_cl = 0.f, a_np = 0.f;

    size_t plane_base = ((size_t)b * 255 + (size_t)a * 85) * PLANE;

#pragma unroll
    for (int u = 0; u < CPT; u++) {
        int lp = tid + u * TPB;
        int p  = p0 + lp;
        if (p >= PLANE) break;

        size_t base = plane_base + p;
        float confl = input[base + (size_t)4 * PLANE];
        float conf  = fsigmoid(confl);
        float conf_c = fminf(fmaxf(conf, EPSF), 1.0f - EPSF);

        int  wt  = s_win[lp];
        bool m   = (wt >= 0);
        bool ign = (s_ign[lp] != 0);

        a_c1 += m      ? (-__logf(conf_c))        : LOG1MEPS;  // bce(conf*mask, mask)
        a_c2 += (!ign) ? (-__logf(1.0f - conf_c)) : LOG1MEPS;  // bce(conf*noobj, 0)

        if (m) {
            a_np += 1.0f;
            int j = p / GW;
            int i = p - j * GW;
            const float* tp = targets + ((size_t)b * T + wt) * 5;
            float kx = tp[1] * GW, ky = tp[2] * GH;
            float kw = tp[3] * GW, kh = tp[4] * GH;

            float xl = input[base];
            float yl = input[base + (size_t)1 * PLANE];
            float wl = input[base + (size_t)2 * PLANE];
            float hl = input[base + (size_t)3 * PLANE];

            float hx = fsigmoid(xl) + (float)i;
            float hy = fsigmoid(yl) + (float)j;
            float hw = __expf(wl) * c_aw[a];
            float hh = __expf(hl) * c_ah[a];

            float iw = fminf(hx + hw * 0.5f, kx + kw * 0.5f) -
                       fmaxf(hx - hw * 0.5f, kx - kw * 0.5f);
            iw = fmaxf(iw, 0.0f);
            float ih = fminf(hy + hh * 0.5f, ky + kh * 0.5f) -
                       fmaxf(hy - hh * 0.5f, ky - kh * 0.5f);
            ih = fmaxf(ih, 0.0f);
            float inter = iw * ih;
            float iou = inter / (hw * hh + kw * kh - inter + 1e-16f);
            a_iou += 1.0f - iou;

            unsigned w0 = s_cls[lp];
            unsigned w1 = s_cls[lp + CHUNK];
            unsigned w2 = s_cls[lp + 2 * CHUNK];
#pragma unroll 8
            for (int c = 0; c < NCLS; c++) {
                float pl = input[base + (size_t)(5 + c) * PLANE];
                float pc = fsigmoid(pl);
                float pp = fminf(fmaxf(pc, EPSF), 1.0f - EPSF);
                unsigned word = (c < 32) ? w0 : (c < 64 ? w1 : w2);
                bool tt = (word >> (c & 31)) & 1u;
                // bce with binary target: -log(t ? p : 1-p)
                a_cl += -__logf(tt ? pp : 1.0f - pp);
            }
        }
    }

    // ---- block reduction (8 warps) ----
    a_iou = warp_sum(a_iou);
    a_c1  = warp_sum(a_c1);
    a_c2  = warp_sum(a_c2);
    a_cl  = warp_sum(a_cl);
    a_np  = warp_sum(a_np);

    int wid = tid >> 5, lid = tid & 31;
    if (lid == 0) {
        s_part[0][wid] = a_iou; s_part[1][wid] = a_c1; s_part[2][wid] = a_c2;
        s_part[3][wid] = a_cl;  s_part[4][wid] = a_np;
    }
    __syncthreads();
    if (wid == 0) {
        float v0 = (lid < 8) ? s_part[0][lid] : 0.f;
        float v1 = (lid < 8) ? s_part[1][lid] : 0.f;
        float v2 = (lid < 8) ? s_part[2][lid] : 0.f;
        float v3 = (lid < 8) ? s_part[3][lid] : 0.f;
        float v4 = (lid < 8) ? s_part[4][lid] : 0.f;
        v0 = warp_sum(v0); v1 = warp_sum(v1); v2 = warp_sum(v2);
        v3 = warp_sum(v3); v4 = warp_sum(v4);
        if (lid == 0) {
            if (v0 != 0.f) atomicAdd(&d_acc[0], (double)v0);
            atomicAdd(&d_acc[1], (double)v1);
            atomicAdd(&d_acc[2], (double)v2);
            if (v3 != 0.f) atomicAdd(&d_acc[3], (double)v3);
            if (v4 != 0.f) atomicAdd(&d_npos, (int)(v4 + 0.5f));
        }
    }

    // ---- last-block finalize + reset (graph-replay safe) ----
    __threadfence();
    if (tid == 0) {
        unsigned prev = atomicAdd(&d_count, 1u);
        s_last = (prev == gridDim.x - 1) ? 1 : 0;
    }
    __syncthreads();
    if (s_last && tid == 0) {
        double iou = d_acc[0], c1 = d_acc[1], c2 = d_acc[2], cls = d_acc[3];
        int np = d_npos;
        double N = (double)B * NA * GH * GW;
        float loss_iou  = (float)iou;
        float loss_conf = (float)(c1 / N + 0.5 * (c2 / N));
        double npf = (np < 1) ? 1.0 : (double)np;
        float loss_cls  = (float)(cls / (npf * (double)NCLS));
        out[0] = 0.5f * loss_iou + loss_conf + loss_cls;
        out[1] = loss_iou;
        out[2] = loss_conf;
        out[3] = loss_cls;
        d_acc[0] = 0.0; d_acc[1] = 0.0; d_acc[2] = 0.0; d_acc[3] = 0.0;
        d_npos = 0;
        d_count = 0u;
    }
}

extern "C" void kernel_launch(void* const* d_in, const int* in_sizes, int n_in,
                              void* d_out, int out_size) {
    const float* input   = (const float*)d_in[0];
    const float* targets = (const float*)d_in[1];

    int B = in_sizes[0] / (255 * GH * GW);
    int T = in_sizes[1] / (B * 5);

    int nblk = B * NA * NCHUNK;   // 32*3*3 = 288
    k_fused<<<nblk, TPB>>>(input, targets, (float*)d_out, B, T);
}

// round 4
// speedup vs baseline: 2.9975x; 2.4550x over previous
#include <cuda_runtime.h>

// ---------------- problem constants ----------------
#define NA 3
#define GH 52
#define GW 52
#define NCLS 80
#define PLANE (GH*GW)             // 2704
#define EPSF 1e-7f
#define LOG1MEPS 1.00000011686097e-07f   // -log(1 - 1e-7)
#define CHUNK 1024                // cells per block (multiple of 4)
#define NCHUNK 3                  // 1024+1024+656 = 2704
#define TPB 256
#define NWARP (TPB/32)

// scaled anchors = ANCHORS / (416/52) = ANCHORS / 8
__constant__ float c_aw[3] = {1.25f, 2.0f, 4.125f};
__constant__ float c_ah[3] = {1.625f, 3.75f, 2.875f};

// ---------------- global accumulators (zero at module load; reset by last block) ----
__device__ double       d_acc[4];     // iou_sum, conf1_sum, conf2_sum, cls_sum
__device__ int          d_npos;
__device__ unsigned int d_count;

__device__ __forceinline__ float warp_sum(float v) {
#pragma unroll
    for (int o = 16; o > 0; o >>= 1) v += __shfl_down_sync(0xffffffffu, v, o);
    return v;
}

__device__ __forceinline__ float fsigmoid(float x) {
    return __fdividef(1.0f, 1.0f + __expf(-x));
}

__global__ void k_fused(const float* __restrict__ input,
                        const float* __restrict__ targets,
                        float* __restrict__ out,
                        int B, int T) {
    // block -> (b, a, chunk)
    int bx    = blockIdx.x;
    int b     = bx / (NA * NCHUNK);
    int rem   = bx % (NA * NCHUNK);
    int a     = rem / NCHUNK;
    int chunk = rem % NCHUNK;
    int p0    = chunk * CHUNK;
    int ncell = min(PLANE - p0, CHUNK);     // 1024 or 656

    __shared__ int           s_win[CHUNK];        // winner target idx, -1 none
    __shared__ unsigned int  s_cls[CHUNK * 3];    // 80-bit class union
    __shared__ unsigned char s_ign[CHUNK];        // 1 => noobj = 0
    __shared__ int           s_mlist[64];         // masked-cell local indices
    __shared__ int           s_nmask;
    __shared__ float         s_part[5][NWARP];
    __shared__ int           s_last;

    int tid = threadIdx.x;
#pragma unroll
    for (int u = 0; u < CHUNK / TPB; u++) {
        int k = tid + u * TPB;
        s_win[k] = -1;
        s_ign[k] = 0;
        s_cls[k] = 0u;
        s_cls[k + CHUNK] = 0u;
        s_cls[k + 2 * CHUNK] = 0u;
    }
    if (tid == 0) s_nmask = 0;
    __syncthreads();

    // ---- in-block target decode ----
    for (int t = tid; t < T; t += TPB) {
        const float* tp = targets + ((size_t)b * T + t) * 5;
        float c = tp[0], x = tp[1], y = tp[2], w = tp[3], h = tp[4];
        if (c + x + y + w + h == 0.0f) continue;          // valid = sum != 0

        float gx = x * GW, gy = y * GH, gw = w * GW, gh = h * GH;
        int gi = (int)gx, gj = (int)gy;
        if (gi < 0 || gi >= GW || gj < 0 || gj >= GH) continue;

        int p  = gj * GW + gi;
        int lp = p - p0;
        if (lp < 0 || lp >= ncell) continue;

        float area = gw * gh;
        float ious[3];
        float best_iou = -1.0f;
        int best = 0;
#pragma unroll
        for (int k = 0; k < 3; k++) {
            float inter = fminf(gw, c_aw[k]) * fminf(gh, c_ah[k]);
            float iou = inter / (area + c_aw[k] * c_ah[k] - inter + 1e-16f);
            ious[k] = iou;
            if (iou > best_iou) { best_iou = iou; best = k; } // argmax (first max)
        }

        if (ious[a] > 0.5f) s_ign[lp] = 1;                 // benign races
        if (best == a) {
            atomicMax(&s_win[lp], t);                      // last-update-wins
            int cls = (int)c;
            if (cls >= 0 && cls < NCLS)
                atomicOr(&s_cls[lp + ((cls >> 5) * CHUNK)], 1u << (cls & 31));
        }
    }
    __syncthreads();

    float a_iou = 0.f, a_c1 = 0.f, a_c2 = 0.f, a_cl = 0.f, a_np = 0.f;
    size_t plane_base = ((size_t)b * 255 + (size_t)a * 85) * PLANE;

    // ---- dense conf sweep (float4, fully coalesced) + masked-list build ----
    int nf4 = ncell >> 2;                     // 256 or 164
    if (tid < nf4) {
        const float4 cv = *reinterpret_cast<const float4*>(
            input + plane_base + (size_t)4 * PLANE + p0 + 4 * tid);
        float cl[4] = {cv.x, cv.y, cv.z, cv.w};
#pragma unroll
        for (int k = 0; k < 4; k++) {
            int lp = 4 * tid + k;
            float conf   = fsigmoid(cl[k]);
            float conf_c = fminf(fmaxf(conf, EPSF), 1.0f - EPSF);
            bool m   = (s_win[lp] >= 0);
            bool ign = (s_ign[lp] != 0);
            a_c1 += m      ? (-__logf(conf_c))        : LOG1MEPS;
            a_c2 += (!ign) ? (-__logf(1.0f - conf_c)) : LOG1MEPS;
            if (m) {
                int idx = atomicAdd(&s_nmask, 1);
                if (idx < 64) s_mlist[idx] = lp;
            }
        }
    }
    __syncthreads();

    // ---- masked cells: one warp per cell, lanes cover channels ----
    int wid = tid >> 5, lid = tid & 31;
    int nmask = min(s_nmask, 64);
    for (int m = wid; m < nmask; m += NWARP) {
        int lp = s_mlist[m];
        int p  = p0 + lp;
        int j  = p / GW;
        int i  = p - j * GW;
        int wt = s_win[lp];
        size_t base = plane_base + p;

        // lane l loads channels l, l+32, l+64 (stride-PLANE scatter, all concurrent)
        float v0 = input[base + (size_t)lid * PLANE];
        float v1 = input[base + (size_t)(lid + 32) * PLANE];
        float v2 = (lid < 21) ? input[base + (size_t)(lid + 64) * PLANE] : 0.0f;

        // broadcast x,y,w,h logits from lanes 0..3
        float xl = __shfl_sync(0xffffffffu, v0, 0);
        float yl = __shfl_sync(0xffffffffu, v0, 1);
        float wl = __shfl_sync(0xffffffffu, v0, 2);
        float hl = __shfl_sync(0xffffffffu, v0, 3);

        const float* tp = targets + ((size_t)b * T + wt) * 5;
        float kx = tp[1] * GW, ky = tp[2] * GH;
        float kw = tp[3] * GW, kh = tp[4] * GH;

        float hx = fsigmoid(xl) + (float)i;
        float hy = fsigmoid(yl) + (float)j;
        float hw = __expf(wl) * c_aw[a];
        float hh = __expf(hl) * c_ah[a];

        float iw = fminf(hx + hw * 0.5f, kx + kw * 0.5f) -
                   fmaxf(hx - hw * 0.5f, kx - kw * 0.5f);
        iw = fmaxf(iw, 0.0f);
        float ih = fminf(hy + hh * 0.5f, ky + kh * 0.5f) -
                   fmaxf(hy - hh * 0.5f, ky - kh * 0.5f);
        ih = fmaxf(ih, 0.0f);
        float inter = iw * ih;
        float iou = inter / (hw * hh + kw * kh - inter + 1e-16f);
        if (lid == 0) { a_iou += 1.0f - iou; a_np += 1.0f; }

        unsigned w0 = s_cls[lp];
        unsigned w1 = s_cls[lp + CHUNK];
        unsigned w2 = s_cls[lp + 2 * CHUNK];

        // class bce: v0 -> classes lid-5 (lid>=5), v1 -> lid+27, v2 -> lid+59 (lid<21)
        float cls_sum = 0.0f;
        if (lid >= 5) {
            int c = lid - 5;                       // 0..26
            float pp = fminf(fmaxf(fsigmoid(v0), EPSF), 1.0f - EPSF);
            bool tt = (w0 >> c) & 1u;
            cls_sum += -__logf(tt ? pp : 1.0f - pp);
        }
        {
            int c = lid + 27;                      // 27..58
            float pp = fminf(fmaxf(fsigmoid(v1), EPSF), 1.0f - EPSF);
            unsigned word = (c < 32) ? w0 : (c < 64 ? w1 : w2);
            bool tt = (word >> (c & 31)) & 1u;
            cls_sum += -__logf(tt ? pp : 1.0f - pp);
        }
        if (lid < 21) {
            int c = lid + 59;                      // 59..79
            float pp = fminf(fmaxf(fsigmoid(v2), EPSF), 1.0f - EPSF);
            bool tt = (w2 >> (c & 31)) & 1u;
            cls_sum += -__logf(tt ? pp : 1.0f - pp);
        }
        a_cl += cls_sum;   // warp-reduced below
    }

    // ---- block reduction ----
    a_iou = warp_sum(a_iou);
    a_c1  = warp_sum(a_c1);
    a_c2  = warp_sum(a_c2);
    a_cl  = warp_sum(a_cl);
    a_np  = warp_sum(a_np);

    if (lid == 0) {
        s_part[0][wid] = a_iou; s_part[1][wid] = a_c1; s_part[2][wid] = a_c2;
        s_part[3][wid] = a_cl;  s_part[4][wid] = a_np;
    }
    __syncthreads();
    if (wid == 0) {
        float v0 = (lid < NWARP) ? s_part[0][lid] : 0.f;
        float v1 = (lid < NWARP) ? s_part[1][lid] : 0.f;
        float v2 = (lid < NWARP) ? s_part[2][lid] : 0.f;
        float v3 = (lid < NWARP) ? s_part[3][lid] : 0.f;
        float v4 = (lid < NWARP) ? s_part[4][lid] : 0.f;
        v0 = warp_sum(v0); v1 = warp_sum(v1); v2 = warp_sum(v2);
        v3 = warp_sum(v3); v4 = warp_sum(v4);
        if (lid == 0) {
            if (v0 != 0.f) atomicAdd(&d_acc[0], (double)v0);
            atomicAdd(&d_acc[1], (double)v1);
            atomicAdd(&d_acc[2], (double)v2);
            if (v3 != 0.f) atomicAdd(&d_acc[3], (double)v3);
            if (v4 != 0.f) atomicAdd(&d_npos, (int)(v4 + 0.5f));
        }
    }

    // ---- last-block finalize + reset (graph-replay safe) ----
    __threadfence();
    if (tid == 0) {
        unsigned prev = atomicAdd(&d_count, 1u);
        s_last = (prev == gridDim.x - 1) ? 1 : 0;
    }
    __syncthreads();
    if (s_last && tid == 0) {
        double iou = d_acc[0], c1 = d_acc[1], c2 = d_acc[2], cls = d_acc[3];
        int np = d_npos;
        double N = (double)B * NA * GH * GW;
        float loss_iou  = (float)iou;
        float loss_conf = (float)(c1 / N + 0.5 * (c2 / N));
        double npf = (np < 1) ? 1.0 : (double)np;
        float loss_cls  = (float)(cls / (npf * (double)NCLS));
        out[0] = 0.5f * loss_iou + loss_conf + loss_cls;
        out[1] = loss_iou;
        out[2] = loss_conf;
        out[3] = loss_cls;
        d_acc[0] = 0.0; d_acc[1] = 0.0; d_acc[2] = 0.0; d_acc[3] = 0.0;
        d_npos = 0;
        d_count = 0u;
    }
}

extern "C" void kernel_launch(void* const* d_in, const int* in_sizes, int n_in,
                              void* d_out, int out_size) {
    const float* input   = (const float*)d_in[0];
    const float* targets = (const float*)d_in[1];

    int B = in_sizes[0] / (255 * GH * GW);
    int T = in_sizes[1] / (B * 5);

    int nblk = B * NA * NCHUNK;   // 32*3*3 = 288
    k_fused<<<nblk, TPB>>>(input, targets, (float*)d_out, B, T);
}